// round 3
// baseline (speedup 1.0000x reference)
#include <cuda_runtime.h>
#include <cstdint>

// ---------------------------------------------------------------------------
// MLP over graph edges, factored:
//   h1 = relu(drug[i] @ W1a^T + dis[j] @ W1b^T + b1)
//      = relu(A[i] + B[j])          with A, B precomputed per node
//   h2 = relu(h1 @ W2^T + b2)       (TF32 tensor-core GEMM, 128 edges/tile)
//   out = h2 @ W3^T + b3            (register epilogue + quad shuffle reduce)
// ---------------------------------------------------------------------------

#define IN_UNITS   128
#define H1_DIM     128
#define H2_DIM     64
#define N_DRUG_MAX 10000
#define N_DIS_MAX  5000
#define N_EDGE_MAX 2000000

#define TILE_E     128
#define H1_STRIDE  132   // pad: conflict-free A-fragment LDS, 16B-aligned rows (528B)
#define W2_STRIDE  132   // pad: conflict-free B-fragment LDS

__device__ __align__(16) float g_A[N_DRUG_MAX * H1_DIM];
__device__ __align__(16) float g_B[N_DIS_MAX * H1_DIM];
__device__ int g_ei[2 * N_EDGE_MAX];   // normalized int32 indices

__device__ __forceinline__ float tf32r(float x) {
    uint32_t u;
    asm("cvt.rna.tf32.f32 %0, %1;" : "=r"(u) : "f"(x));
    return __uint_as_float(u);
}

__device__ __forceinline__ void mma_m16n8k8_tf32(float acc[4],
        uint32_t a0, uint32_t a1, uint32_t a2, uint32_t a3,
        uint32_t b0, uint32_t b1) {
    asm volatile(
        "mma.sync.aligned.m16n8k8.row.col.f32.tf32.tf32.f32 "
        "{%0,%1,%2,%3}, {%4,%5,%6,%7}, {%8,%9}, {%0,%1,%2,%3};\n"
        : "+f"(acc[0]), "+f"(acc[1]), "+f"(acc[2]), "+f"(acc[3])
        : "r"(a0), "r"(a1), "r"(a2), "r"(a3), "r"(b0), "r"(b1));
}

// ---------------------------------------------------------------------------
// Index normalization. The harness may hand edge_index as int32 (downcast of
// the reference's int64) or as genuine int64. Detect on-device: with int64
// data every value is < 5000, so the hi 32 bits of each word are zero; with
// int32 data the hi word is the *next* index (nonzero w.p. 4999/5000).
// Checking 64 words makes misdetection probability ~(1/5000)^64 = 0.
// Deterministic w.r.t. input data -> graph/replay safe.
// ---------------------------------------------------------------------------
__global__ void normalize_idx(const void* __restrict__ raw, int n_total) {
    const unsigned long long* r64 = (const unsigned long long*)raw;
    const int* r32 = (const int*)raw;

    bool is64 = true;
    #pragma unroll
    for (int k = 0; k < 64; k++)
        if (r64[k] >> 32) { is64 = false; break; }

    int t = blockIdx.x * blockDim.x + threadIdx.x;
    if (t < n_total)
        g_ei[t] = is64 ? (int)((const long long*)raw)[t] : r32[t];
}

// ---------------------------------------------------------------------------
// Precompute: A[row] = drug_feat[row] @ W1[:, 0:128]^T
//             B[row] = dis_feat[row]  @ W1[:, 128:256]^T + b1
// ---------------------------------------------------------------------------
#define RPB 4

__global__ void precompute_A(const float* __restrict__ feat,
                             const float* __restrict__ W1, int nrows) {
    int row0 = blockIdx.x * RPB;
    int c = threadIdx.x;  // output channel 0..127
    __shared__ float sf[RPB][IN_UNITS];
    for (int r = 0; r < RPB; r++) {
        int row = row0 + r;
        sf[r][c] = (row < nrows) ? feat[row * IN_UNITS + c] : 0.f;
    }
    __syncthreads();
    float acc[RPB] = {0.f, 0.f, 0.f, 0.f};
    const float4* w = (const float4*)(W1 + c * (2 * IN_UNITS));
#pragma unroll
    for (int k = 0; k < IN_UNITS / 4; k++) {
        float4 ww = w[k];
#pragma unroll
        for (int r = 0; r < RPB; r++) {
            float4 f = *(const float4*)&sf[r][k * 4];
            acc[r] += f.x * ww.x + f.y * ww.y + f.z * ww.z + f.w * ww.w;
        }
    }
    for (int r = 0; r < RPB; r++) {
        int row = row0 + r;
        if (row < nrows) g_A[row * H1_DIM + c] = acc[r];
    }
}

__global__ void precompute_B(const float* __restrict__ feat,
                             const float* __restrict__ W1,
                             const float* __restrict__ b1, int nrows) {
    int row0 = blockIdx.x * RPB;
    int c = threadIdx.x;
    __shared__ float sf[RPB][IN_UNITS];
    for (int r = 0; r < RPB; r++) {
        int row = row0 + r;
        sf[r][c] = (row < nrows) ? feat[row * IN_UNITS + c] : 0.f;
    }
    __syncthreads();
    float b1c = b1[c];
    float acc[RPB] = {b1c, b1c, b1c, b1c};
    const float4* w = (const float4*)(W1 + c * (2 * IN_UNITS) + IN_UNITS);
#pragma unroll
    for (int k = 0; k < IN_UNITS / 4; k++) {
        float4 ww = w[k];
#pragma unroll
        for (int r = 0; r < RPB; r++) {
            float4 f = *(const float4*)&sf[r][k * 4];
            acc[r] += f.x * ww.x + f.y * ww.y + f.z * ww.z + f.w * ww.w;
        }
    }
    for (int r = 0; r < RPB; r++) {
        int row = row0 + r;
        if (row < nrows) g_B[row * H1_DIM + c] = acc[r];
    }
}

// ---------------------------------------------------------------------------
// Main fused kernel: per 128-edge tile
//   phase A (per warp, 16 edges): gather relu(A[i]+B[j]) -> SMEM (tf32-rounded)
//   phase B: warp-private 16x64x128 TF32 MMA against W2 (SMEM)
//   phase C: bias + relu + W3 dot in registers, quad shuffle reduce, store
// H1 rows are warp-private -> no __syncthreads in the tile loop.
// ---------------------------------------------------------------------------
__global__ __launch_bounds__(256, 1)
void edge_mlp_kernel(const float* __restrict__ W2,
                     const float* __restrict__ b2,
                     const float* __restrict__ W3,
                     const float* __restrict__ b3,
                     float* __restrict__ out,
                     int E, int ntiles) {
    extern __shared__ float smem[];
    float* H1  = smem;                         // TILE_E * H1_STRIDE
    float* W2s = H1 + TILE_E * H1_STRIDE;      // H2_DIM * W2_STRIDE
    float* b2s = W2s + H2_DIM * W2_STRIDE;     // H2_DIM
    float* w3s = b2s + H2_DIM;                 // H2_DIM

    int tid = threadIdx.x;

    // Stage W2 (tf32-rounded), b2, W3 once per CTA.
    for (int t = tid; t < H2_DIM * H1_DIM; t += blockDim.x) {
        int n = t >> 7, k = t & 127;
        W2s[n * W2_STRIDE + k] = tf32r(W2[t]);
    }
    if (tid < H2_DIM) { b2s[tid] = b2[tid]; w3s[tid] = W3[tid]; }
    __syncthreads();
    float b3v = __ldg(b3);

    int warp = tid >> 5;
    int lane = tid & 31;
    int g  = lane >> 2;   // mma groupID (row within 16-edge tile)
    int tg = lane & 3;    // mma thread-in-group (k / n sub-index)
    float* Hrow = H1 + warp * 16 * H1_STRIDE;

    for (int tile = blockIdx.x; tile < ntiles; tile += gridDim.x) {
        int ebase = tile * TILE_E + warp * 16;

        // Coalesced index load: lanes 0..15 -> drug idx, 16..31 -> dis idx.
        int le = lane & 15;
        int e = ebase + le;
        int myidx = 0;
        if (e < E)
            myidx = (lane < 16) ? g_ei[e] : g_ei[E + e];

        // ---- gather: h1 = tf32(relu(A[i] + B[j])) into warp-private SMEM ----
#pragma unroll 4
        for (int q = 0; q < 16; q++) {
            int i = __shfl_sync(0xffffffffu, myidx, q);
            int j = __shfl_sync(0xffffffffu, myidx, 16 + q);
            float4 a = *(const float4*)(g_A + i * H1_DIM + lane * 4);
            float4 b = *(const float4*)(g_B + j * H1_DIM + lane * 4);
            float4 v;
            v.x = tf32r(fmaxf(a.x + b.x, 0.f));
            v.y = tf32r(fmaxf(a.y + b.y, 0.f));
            v.z = tf32r(fmaxf(a.z + b.z, 0.f));
            v.w = tf32r(fmaxf(a.w + b.w, 0.f));
            *(float4*)(Hrow + q * H1_STRIDE + lane * 4) = v;
        }
        __syncwarp();

        // ---- layer 2: 16(edges) x 64(ch) x 128(k) TF32 MMA ----
        float acc[8][4];
#pragma unroll
        for (int n = 0; n < 8; n++)
            acc[n][0] = acc[n][1] = acc[n][2] = acc[n][3] = 0.f;

#pragma unroll
        for (int s = 0; s < 16; s++) {
            int k0 = s * 8;
            uint32_t a0 = __float_as_uint(Hrow[g * H1_STRIDE + k0 + tg]);
            uint32_t a1 = __float_as_uint(Hrow[(g + 8) * H1_STRIDE + k0 + tg]);
            uint32_t a2 = __float_as_uint(Hrow[g * H1_STRIDE + k0 + tg + 4]);
            uint32_t a3 = __float_as_uint(Hrow[(g + 8) * H1_STRIDE + k0 + tg + 4]);
#pragma unroll
            for (int n = 0; n < 8; n++) {
                uint32_t b0 = __float_as_uint(W2s[(n * 8 + g) * W2_STRIDE + k0 + tg]);
                uint32_t b1 = __float_as_uint(W2s[(n * 8 + g) * W2_STRIDE + k0 + tg + 4]);
                mma_m16n8k8_tf32(acc[n], a0, a1, a2, a3, b0, b1);
            }
        }

        // ---- epilogue: relu(h2 + b2) . W3 + b3, reduced across the quad ----
        float o0 = 0.f, o1 = 0.f;
#pragma unroll
        for (int n = 0; n < 8; n++) {
            int c0 = n * 8 + 2 * tg;
            float bb0 = b2s[c0], bb1 = b2s[c0 + 1];
            float w0 = w3s[c0],  w1 = w3s[c0 + 1];
            o0 += fmaxf(acc[n][0] + bb0, 0.f) * w0 + fmaxf(acc[n][1] + bb1, 0.f) * w1;
            o1 += fmaxf(acc[n][2] + bb0, 0.f) * w0 + fmaxf(acc[n][3] + bb1, 0.f) * w1;
        }
        o0 += __shfl_xor_sync(0xffffffffu, o0, 1);
        o0 += __shfl_xor_sync(0xffffffffu, o0, 2);
        o1 += __shfl_xor_sync(0xffffffffu, o1, 1);
        o1 += __shfl_xor_sync(0xffffffffu, o1, 2);
        if (tg == 0) {
            int e0 = ebase + g;
            int e1 = ebase + g + 8;
            if (e0 < E) out[e0] = o0 + b3v;
            if (e1 < E) out[e1] = o1 + b3v;
        }
        __syncwarp();   // next tile's gather rewrites rows this warp just read
    }
}

// ---------------------------------------------------------------------------
// Launch
// ---------------------------------------------------------------------------
extern "C" void kernel_launch(void* const* d_in, const int* in_sizes, int n_in,
                              void* d_out, int out_size) {
    const float* drug = (const float*)d_in[0];
    const float* dis  = (const float*)d_in[1];
    const void*  eraw = d_in[2];
    const float* W1   = (const float*)d_in[3];
    const float* b1   = (const float*)d_in[4];
    const float* W2   = (const float*)d_in[5];
    const float* b2   = (const float*)d_in[6];
    const float* W3   = (const float*)d_in[7];
    const float* b3   = (const float*)d_in[8];
    float* out = (float*)d_out;

    int n_drug  = in_sizes[0] / IN_UNITS;
    int n_dis   = in_sizes[1] / IN_UNITS;
    int n_total = in_sizes[2];       // 2*E elements regardless of dtype
    int E       = n_total / 2;
    int ntiles  = (E + TILE_E - 1) / TILE_E;

    normalize_idx<<<(n_total + 255) / 256, 256>>>(eraw, n_total);
    precompute_A<<<(n_drug + RPB - 1) / RPB, IN_UNITS>>>(drug, W1, n_drug);
    precompute_B<<<(n_dis + RPB - 1) / RPB, IN_UNITS>>>(dis, W1, b1, n_dis);

    constexpr int smem_bytes =
        (TILE_E * H1_STRIDE + H2_DIM * W2_STRIDE + 2 * H2_DIM) * 4;
    cudaFuncSetAttribute(edge_mlp_kernel,
                         cudaFuncAttributeMaxDynamicSharedMemorySize,
                         smem_bytes);

    int grid = 296;  // ~2 persistent CTAs per SM
    if (grid > ntiles) grid = ntiles;
    edge_mlp_kernel<<<grid, 256, smem_bytes>>>(W2, b2, W3, b3, out, E, ntiles);
}